// round 10
// baseline (speedup 1.0000x reference)
#include <cuda_runtime.h>

#define SEQ   96
#define PRED  16
#define HID   64
#define FEAT  7
#define BPB   4               // batches per block
#define NBLK  128             // 512/4 — one block per SM, single wave
#define NTHR  512
#define WIN   (SEQ + PRED)

typedef unsigned long long ull;

static __device__ __forceinline__ ull pack2(float a, float b){
    ull r; asm("mov.b64 %0, {%1, %2};" : "=l"(r) : "f"(a), "f"(b)); return r;
}
static __device__ __forceinline__ void unpack2(ull v, float &a, float &b){
    asm("mov.b64 {%0, %1}, %2;" : "=f"(a), "=f"(b) : "l"(v));
}
// d = a*b + d, packed f32x2 (Blackwell FFMA2), exact fp32 per lane
static __device__ __forceinline__ void ffma2(ull &d, ull a, ull b){
    asm("fma.rn.f32x2 %0, %1, %2, %0;" : "+l"(d) : "l"(a), "l"(b));
}

static __device__ __forceinline__ float sigmoid_fast(float x){
    float e = __expf(-x);
    return __fdividef(1.0f, 1.0f + e);
}
static __device__ __forceinline__ float tanhf_fast(float x){
    float e = __expf(-2.0f * x);
    return __fdividef(2.0f, 1.0f + e) - 1.0f;
}

__global__ void __launch_bounds__(NTHR, 1)
lstm_ar_kernel(const float* __restrict__ x,
               const float* __restrict__ W_ih,
               const float* __restrict__ W_hh,
               const float* __restrict__ b_ih,
               const float* __restrict__ b_hh,
               const float* __restrict__ fc_W,
               const float* __restrict__ fc_b,
               float* __restrict__ out)
{
    // sliding input window: [t][feat][b], b in [0,4)
    __shared__ float sh_xw[WIN * FEAT * BPB];
    // hidden state, double-buffered, batch-major: [buf][b][u]
    __shared__ float h_sh[2][BPB][HID];
    __shared__ float sh_fcW[FEAT * HID];
    __shared__ float sh_fcb[FEAT];

    const int tid = threadIdx.x;            // 0..511
    const int kh  = tid & 1;                // K-half: cols [32kh, 32kh+32)
    const int gp  = (tid >> 1) & 1;         // 0: rows i,f   1: rows g,o
    const int u   = (tid >> 2) & 63;        // hidden unit
    const int bp  = tid >> 8;               // batch pair: batches (2bp, 2bp+1)
    const int rA  = gp * 128 + u;           // i-row (gp0) / g-row (gp1)
    const int rB  = gp * 128 + 64 + u;      // f-row (gp0) / o-row (gp1)
    const int bO  = 2 * bp + gp;            // batch whose cell state this thread owns
    const int b0  = blockIdx.x * BPB;

    // ---------------- one-time init ----------------
    for (int i = tid; i < SEQ * FEAT * BPB; i += NTHR){
        int b = i & 3;
        int q = i >> 2;
        int f = q % FEAT;
        int t = q / FEAT;
        sh_xw[(t * FEAT + f) * BPB + b] =
            x[(size_t)(b0 + b) * SEQ * FEAT + t * FEAT + f];
    }
    for (int i = tid; i < FEAT * HID; i += NTHR) sh_fcW[i] = fc_W[i];
    if (tid < FEAT) sh_fcb[tid] = fc_b[tid];
    {
        float* hz = &h_sh[0][0][0];
        for (int i = tid; i < 2 * BPB * HID; i += NTHR) hz[i] = 0.0f;
    }

    // W_hh row slices (this thread's K-half), natural column-pairs: 32 ull = 64 regs
    ull whhA[16], whhB[16];
    {
        const ull* wa = reinterpret_cast<const ull*>(W_hh + (size_t)rA * HID + kh * 32);
        const ull* wb = reinterpret_cast<const ull*>(W_hh + (size_t)rB * HID + kh * 32);
        #pragma unroll
        for (int c = 0; c < 16; c++){ whhA[c] = wa[c]; whhB[c] = wb[c]; }
    }
    // x-projection split across K-halves: kh0 -> feats 0..3, kh1 -> feats 4..6 (+zero pad)
    ull wihA2[4], wihB2[4];
    #pragma unroll
    for (int f = 0; f < 4; f++){
        int ff = kh * 4 + f;
        float wa = (ff < FEAT) ? W_ih[rA * FEAT + ff] : 0.0f;
        float wb = (ff < FEAT) ? W_ih[rB * FEAT + ff] : 0.0f;
        wihA2[f] = pack2(wa, wa);
        wihB2[f] = pack2(wb, wb);
    }
    // bias seeded on kh=0 only (even lane of the col-pair acc)
    const ull seedA = (kh == 0) ? pack2(b_ih[rA] + b_hh[rA], 0.0f) : 0ull;
    const ull seedB = (kh == 0) ? pack2(b_ih[rB] + b_hh[rB], 0.0f) : 0ull;

    float c_reg = 0.0f;        // cell state of (batch bO, unit u) — both kh lanes replicate
    int p = 0;

    __syncthreads();

    // ---------------- 16 AR iterations x 96 recurrent steps ----------------
    for (int k = 0; k < PRED; k++){
        for (int t = 0; t < SEQ; t++){
            const int s = k + t;

            // ---- 4 partial dots: rows (rA,rB) x batches (2bp, 2bp+1), 32 cols ----
            ull aA0 = seedA, aA1 = seedA;       // row A, batch even / odd
            ull aB0 = seedB, aB1 = seedB;       // row B
            const ulonglong2* hE =
                reinterpret_cast<const ulonglong2*>(&h_sh[p][2*bp    ][0]) + kh * 8;
            const ulonglong2* hO =
                reinterpret_cast<const ulonglong2*>(&h_sh[p][2*bp + 1][0]) + kh * 8;
            #pragma unroll
            for (int c = 0; c < 8; c++){
                ulonglong2 u0 = hE[c];          // 4 cols, batch even (broadcast LDS.128)
                ulonglong2 u1 = hO[c];          // batch odd
                ffma2(aA0, u0.x, whhA[2*c]);
                ffma2(aB0, u0.x, whhB[2*c]);
                ffma2(aA0, u0.y, whhA[2*c+1]);
                ffma2(aB0, u0.y, whhB[2*c+1]);
                ffma2(aA1, u1.x, whhA[2*c]);
                ffma2(aB1, u1.x, whhB[2*c]);
                ffma2(aA1, u1.y, whhA[2*c+1]);
                ffma2(aB1, u1.y, whhB[2*c+1]);
            }
            // x-projection partial (this K-half's feats), packed over the batch pair
            ull xA = pack2(0.f, 0.f), xB = xA;
            {
                const float* xrow = &sh_xw[s * FEAT * BPB + 2 * bp];
                #pragma unroll
                for (int f = 0; f < 4; f++){
                    // ff = kh*4+f; ff==7 reads 1 slot past feat range but weight is 0
                    ull xx = *reinterpret_cast<const ull*>(xrow + (kh * 4 + f) * BPB);
                    ffma2(xA, xx, wihA2[f]);
                    ffma2(xB, xx, wihB2[f]);
                }
            }
            float xa0, xa1, xb0, xb1, e, o;
            unpack2(xA, xa0, xa1);
            unpack2(xB, xb0, xb1);
            float vA0, vA1, vB0, vB1;
            unpack2(aA0, e, o); vA0 = (e + o) + xa0;   // rowA, batch even (partial)
            unpack2(aA1, e, o); vA1 = (e + o) + xa1;
            unpack2(aB0, e, o); vB0 = (e + o) + xb0;
            unpack2(aB1, e, o); vB1 = (e + o) + xb1;

            // ---- combine K-halves: partner = lane^1 ----
            vA0 += __shfl_xor_sync(0xffffffffu, vA0, 1);
            vA1 += __shfl_xor_sync(0xffffffffu, vA1, 1);
            vB0 += __shfl_xor_sync(0xffffffffu, vB0, 1);
            vB1 += __shfl_xor_sync(0xffffffffu, vB1, 1);

            // ---- gate-pair exchange (R7-verified pattern, partner = lane^2) ----
            // gp0 owns batch even -> needs (g,o) even; sends (i,f) odd.
            // gp1 owns batch odd  -> needs (i,f) odd;  sends (g,o) even.
            float sA = gp ? vA0 : vA1;
            float sB = gp ? vB0 : vB1;
            float rAv = __shfl_xor_sync(0xffffffffu, sA, 2);
            float rBv = __shfl_xor_sync(0xffffffffu, sB, 2);
            float pi = gp ? rAv : vA0;
            float pf = gp ? rBv : vB0;
            float pg = gp ? vA1 : rAv;
            float po = gp ? vB1 : rBv;

            // ---- activations + cell update for (bO, u); both kh lanes replicate ----
            float gi = sigmoid_fast(pi);
            float gf = sigmoid_fast(pf);
            float gg = tanhf_fast(pg);
            float go = sigmoid_fast(po);
            c_reg = fmaf(gf, c_reg, gi * gg);
            float hv = go * tanhf_fast(c_reg);
            if (!kh) h_sh[p ^ 1][bO][u] = hv;

            __syncthreads();                 // single barrier per step
            p ^= 1;
        }

        // ---- fc head: pred = h @ fc_W^T + fc_b; append to window; emit ----
        if (tid < FEAT * BPB){
            int b  = tid / FEAT;
            int o2 = tid - b * FEAT;
            float acc = sh_fcb[o2];
            #pragma unroll
            for (int jj = 0; jj < HID; jj++)
                acc += h_sh[p][b][jj] * sh_fcW[o2 * HID + jj];
            out[(size_t)(b0 + b) * PRED * FEAT + k * FEAT + o2] = acc;
            sh_xw[((SEQ + k) * FEAT + o2) * BPB + b] = acc;
        }
        __syncthreads();
    }
}

extern "C" void kernel_launch(void* const* d_in, const int* in_sizes, int n_in,
                              void* d_out, int out_size)
{
    const float* x    = (const float*)d_in[0];
    const float* W_ih = (const float*)d_in[1];
    const float* W_hh = (const float*)d_in[2];
    const float* b_ih = (const float*)d_in[3];
    const float* b_hh = (const float*)d_in[4];
    const float* fc_W = (const float*)d_in[5];
    const float* fc_b = (const float*)d_in[6];
    float* out = (float*)d_out;

    lstm_ar_kernel<<<NBLK, NTHR>>>(x, W_ih, W_hh, b_ih, b_hh, fc_W, fc_b, out);
}

// round 11
// speedup vs baseline: 1.4262x; 1.4262x over previous
#include <cuda_runtime.h>

#define SEQ   96
#define PRED  16
#define HID   64
#define FEAT  7
#define BPB   4               // batches per block
#define NBLK  128             // 512/4 — one block per SM, single wave
#define NTHR  256
#define WIN   (SEQ + PRED)

typedef unsigned long long ull;

static __device__ __forceinline__ ull pack2(float a, float b){
    ull r; asm("mov.b64 %0, {%1, %2};" : "=l"(r) : "f"(a), "f"(b)); return r;
}
static __device__ __forceinline__ void unpack2(ull v, float &a, float &b){
    asm("mov.b64 {%0, %1}, %2;" : "=f"(a), "=f"(b) : "l"(v));
}
// d = a*b + d, packed f32x2 (Blackwell FFMA2), exact fp32 per lane
static __device__ __forceinline__ void ffma2(ull &d, ull a, ull b){
    asm("fma.rn.f32x2 %0, %1, %2, %0;" : "+l"(d) : "l"(a), "l"(b));
}

static __device__ __forceinline__ float sigmoid_fast(float x){
    float e = __expf(-x);
    return __fdividef(1.0f, 1.0f + e);
}
static __device__ __forceinline__ float tanhf_fast(float x){
    float e = __expf(-2.0f * x);
    return __fdividef(2.0f, 1.0f + e) - 1.0f;
}

__global__ void __launch_bounds__(NTHR, 1)
lstm_ar_kernel(const float* __restrict__ x,
               const float* __restrict__ W_ih,
               const float* __restrict__ W_hh,
               const float* __restrict__ b_ih,
               const float* __restrict__ b_hh,
               const float* __restrict__ fc_W,
               const float* __restrict__ fc_b,
               float* __restrict__ out)
{
    // sliding input window: [t][feat][b], b in [0,4)
    __shared__ float sh_xw[WIN * FEAT * BPB];
    // hidden state, double-buffered, batch-major: [buf][b][u]
    __shared__ float h_sh[2][BPB][HID];
    __shared__ float sh_fcW[FEAT * HID];
    __shared__ float sh_fcb[FEAT];

    const int tid = threadIdx.x;            // 0..255
    const int bp  = tid >> 7;               // batch pair: batches (2bp, 2bp+1) — warp-aligned
    const int gp  = tid & 1;                // 0: rows i,f   1: rows g,o
    const int u   = (tid >> 1) & 63;        // hidden unit
    const int rA  = gp * 128 + u;           // i-row (gp0) / g-row (gp1)
    const int rB  = gp * 128 + 64 + u;      // f-row (gp0) / o-row (gp1)
    const int bO  = 2 * bp + gp;            // batch whose cell state this thread owns
    const int b0  = blockIdx.x * BPB;
    const int barid = 1 + bp;               // named barrier per half (128 threads each)

    // ---------------- one-time init ----------------
    for (int i = tid; i < SEQ * FEAT * BPB; i += NTHR){
        int b = i & 3;
        int q = i >> 2;
        int f = q % FEAT;
        int t = q / FEAT;
        sh_xw[(t * FEAT + f) * BPB + b] =
            x[(size_t)(b0 + b) * SEQ * FEAT + t * FEAT + f];
    }
    for (int i = tid; i < FEAT * HID; i += NTHR) sh_fcW[i] = fc_W[i];
    if (tid < FEAT) sh_fcb[tid] = fc_b[tid];
    {
        float* hz = &h_sh[0][0][0];
        for (int i = tid; i < 2 * BPB * HID; i += NTHR) hz[i] = 0.0f;
    }

    // W_hh rows rA, rB as natural column-pairs: 64 u64 = 128 regs
    ull whhA[HID / 2], whhB[HID / 2];
    {
        const ull* wa = reinterpret_cast<const ull*>(W_hh + (size_t)rA * HID);
        const ull* wb = reinterpret_cast<const ull*>(W_hh + (size_t)rB * HID);
        #pragma unroll
        for (int c = 0; c < HID / 2; c++){ whhA[c] = wa[c]; whhB[c] = wb[c]; }
    }
    // W_ih rows, splatted for batch-pair f32x2 x-projection
    ull wihA2[FEAT], wihB2[FEAT];
    #pragma unroll
    for (int f = 0; f < FEAT; f++){
        float wa = W_ih[rA * FEAT + f];
        float wb = W_ih[rB * FEAT + f];
        wihA2[f] = pack2(wa, wa);
        wihB2[f] = pack2(wb, wb);
    }
    const ull seedA = pack2(b_ih[rA] + b_hh[rA], 0.0f);
    const ull seedB = pack2(b_ih[rB] + b_hh[rB], 0.0f);

    float c_reg = 0.0f;        // cell state of (batch bO, unit u)
    int p = 0;

    __syncthreads();

    // ---------------- 16 AR iterations x 96 recurrent steps ----------------
    for (int k = 0; k < PRED; k++){
        for (int t = 0; t < SEQ; t++){
            // ---- 4 dots: rows (rA,rB) x batches (2bp, 2bp+1) ----
            ull aA0 = seedA, aA1 = seedA;       // row A, batch even / odd
            ull aB0 = seedB, aB1 = seedB;       // row B
            const ulonglong2* hE =
                reinterpret_cast<const ulonglong2*>(&h_sh[p][2*bp    ][0]);
            const ulonglong2* hO =
                reinterpret_cast<const ulonglong2*>(&h_sh[p][2*bp + 1][0]);
            #pragma unroll
            for (int c = 0; c < 16; c++){
                ulonglong2 u0 = hE[c];          // cols 4c..4c+3, batch even (broadcast)
                ulonglong2 u1 = hO[c];          // batch odd
                ffma2(aA0, u0.x, whhA[2*c]);
                ffma2(aB0, u0.x, whhB[2*c]);
                ffma2(aA0, u0.y, whhA[2*c+1]);
                ffma2(aB0, u0.y, whhB[2*c+1]);
                ffma2(aA1, u1.x, whhA[2*c]);
                ffma2(aB1, u1.x, whhB[2*c]);
                ffma2(aA1, u1.y, whhA[2*c+1]);
                ffma2(aB1, u1.y, whhB[2*c+1]);
            }
            // x-projection packed over the batch pair
            ull xA = pack2(0.f, 0.f), xB = xA;
            {
                const float* xrow = &sh_xw[(k + t) * FEAT * BPB + 2 * bp];
                #pragma unroll
                for (int f = 0; f < FEAT; f++){
                    ull xx = *reinterpret_cast<const ull*>(xrow + f * BPB);
                    ffma2(xA, xx, wihA2[f]);
                    ffma2(xB, xx, wihB2[f]);
                }
            }
            float xa0, xa1, xb0, xb1, e, o;
            unpack2(xA, xa0, xa1);
            unpack2(xB, xb0, xb1);
            float vA0, vA1, vB0, vB1;
            unpack2(aA0, e, o); vA0 = (e + o) + xa0;   // rowA, batch even
            unpack2(aA1, e, o); vA1 = (e + o) + xa1;   // rowA, batch odd
            unpack2(aB0, e, o); vB0 = (e + o) + xb0;   // rowB, batch even
            unpack2(aB1, e, o); vB1 = (e + o) + xb1;   // rowB, batch odd

            // ---- pair exchange: 2 shfl.xor with lane^1 (gp partner) ----
            // gp0 owns batch even -> needs (g,o) even; sends (i,f) odd.
            // gp1 owns batch odd  -> needs (i,f) odd;  sends (g,o) even.
            float sA = gp ? vA0 : vA1;
            float sB = gp ? vB0 : vB1;
            float rAv = __shfl_xor_sync(0xffffffffu, sA, 1);
            float rBv = __shfl_xor_sync(0xffffffffu, sB, 1);
            float pi = gp ? rAv : vA0;
            float pf = gp ? rBv : vB0;
            float pg = gp ? vA1 : rAv;
            float po = gp ? vB1 : rBv;

            // ---- activations + cell update for (bO, u) ----
            float gi = sigmoid_fast(pi);
            float gf = sigmoid_fast(pf);
            float gg = tanhf_fast(pg);
            float go = sigmoid_fast(po);
            c_reg = fmaf(gf, c_reg, gi * gg);
            h_sh[p ^ 1][bO][u] = go * tanhf_fast(c_reg);

            // per-half named barrier: the two batch-pair halves are independent,
            // letting them drift so one half's compute covers the other's tail
            asm volatile("bar.sync %0, 128;" :: "r"(barid) : "memory");
            p ^= 1;
        }

        // re-couple the halves: fc head reads h of all 4 batches
        __syncthreads();

        // ---- fc head: pred = h @ fc_W^T + fc_b; append to window; emit ----
        if (tid < FEAT * BPB){
            int b  = tid / FEAT;
            int o2 = tid - b * FEAT;
            float acc = sh_fcb[o2];
            #pragma unroll
            for (int jj = 0; jj < HID; jj++)
                acc += h_sh[p][b][jj] * sh_fcW[o2 * HID + jj];
            out[(size_t)(b0 + b) * PRED * FEAT + k * FEAT + o2] = acc;
            sh_xw[((SEQ + k) * FEAT + o2) * BPB + b] = acc;
        }
        __syncthreads();
    }
}

extern "C" void kernel_launch(void* const* d_in, const int* in_sizes, int n_in,
                              void* d_out, int out_size)
{
    const float* x    = (const float*)d_in[0];
    const float* W_ih = (const float*)d_in[1];
    const float* W_hh = (const float*)d_in[2];
    const float* b_ih = (const float*)d_in[3];
    const float* b_hh = (const float*)d_in[4];
    const float* fc_W = (const float*)d_in[5];
    const float* fc_b = (const float*)d_in[6];
    float* out = (float*)d_out;

    lstm_ar_kernel<<<NBLK, NTHR>>>(x, W_ih, W_hh, b_ih, b_hh, fc_W, fc_b, out);
}

// round 12
// speedup vs baseline: 1.4621x; 1.0252x over previous
#include <cuda_runtime.h>

#define SEQ   96
#define PRED  16
#define HID   64
#define FEAT  7
#define BPB   4               // batches per block
#define NBLK  128             // 512/4 — one block per SM, single wave
#define NTHR  256
#define WIN   (SEQ + PRED)

typedef unsigned long long ull;

static __device__ __forceinline__ ull pack2(float a, float b){
    ull r; asm("mov.b64 %0, {%1, %2};" : "=l"(r) : "f"(a), "f"(b)); return r;
}
static __device__ __forceinline__ void unpack2(ull v, float &a, float &b){
    asm("mov.b64 {%0, %1}, %2;" : "=f"(a), "=f"(b) : "l"(v));
}
// d = a*b + d, packed f32x2 (Blackwell FFMA2), exact fp32 per lane
static __device__ __forceinline__ void ffma2(ull &d, ull a, ull b){
    asm("fma.rn.f32x2 %0, %1, %2, %0;" : "+l"(d) : "l"(a), "l"(b));
}

static __device__ __forceinline__ float sigmoid_fast(float x){
    float e = __expf(-x);
    return __fdividef(1.0f, 1.0f + e);
}
static __device__ __forceinline__ float tanhf_fast(float x){
    float e = __expf(-2.0f * x);
    return __fdividef(2.0f, 1.0f + e) - 1.0f;
}

__global__ void __launch_bounds__(NTHR, 1)
lstm_ar_kernel(const float* __restrict__ x,
               const float* __restrict__ W_ih,
               const float* __restrict__ W_hh,
               const float* __restrict__ b_ih,
               const float* __restrict__ b_hh,
               const float* __restrict__ fc_W,
               const float* __restrict__ fc_b,
               float* __restrict__ out)
{
    // sliding input window: [t][feat][b], b in [0,4)  (per-batch columns)
    __shared__ float sh_xw[WIN * FEAT * BPB];
    // hidden state, double-buffered, batch-major: [buf][b][u]
    __shared__ float h_sh[2][BPB][HID];
    __shared__ float sh_fcW[FEAT * HID];
    __shared__ float sh_fcb[FEAT];

    const int tid = threadIdx.x;            // 0..255
    const int bp  = tid >> 7;               // batch pair (warp-aligned half)
    const int gp  = tid & 1;                // 0: rows i,f   1: rows g,o
    const int u   = (tid >> 1) & 63;        // hidden unit
    const int rA  = gp * 128 + u;           // i-row (gp0) / g-row (gp1)
    const int rB  = gp * 128 + 64 + u;      // f-row (gp0) / o-row (gp1)
    const int bO  = 2 * bp + gp;            // batch whose cell state this thread owns
    const int b0  = blockIdx.x * BPB;
    const int barid = 1 + bp;               // named barrier per independent half
    const int tl  = tid & 127;              // index within half

    // ---------------- one-time init ----------------
    for (int i = tid; i < SEQ * FEAT * BPB; i += NTHR){
        int b = i & 3;
        int q = i >> 2;
        int f = q % FEAT;
        int t = q / FEAT;
        sh_xw[(t * FEAT + f) * BPB + b] =
            x[(size_t)(b0 + b) * SEQ * FEAT + t * FEAT + f];
    }
    for (int i = tid; i < FEAT * HID; i += NTHR) sh_fcW[i] = fc_W[i];
    if (tid < FEAT) sh_fcb[tid] = fc_b[tid];
    {
        float* hz = &h_sh[0][0][0];
        for (int i = tid; i < 2 * BPB * HID; i += NTHR) hz[i] = 0.0f;
    }

    // W_hh rows rA, rB as natural column-pairs: 64 u64 = 128 regs
    ull whhA[HID / 2], whhB[HID / 2];
    {
        const ull* wa = reinterpret_cast<const ull*>(W_hh + (size_t)rA * HID);
        const ull* wb = reinterpret_cast<const ull*>(W_hh + (size_t)rB * HID);
        #pragma unroll
        for (int c = 0; c < HID / 2; c++){ whhA[c] = wa[c]; whhB[c] = wb[c]; }
    }
    // W_ih rows, splatted for batch-pair f32x2 x-projection
    ull wihA2[FEAT], wihB2[FEAT];
    #pragma unroll
    for (int f = 0; f < FEAT; f++){
        float wa = W_ih[rA * FEAT + f];
        float wb = W_ih[rB * FEAT + f];
        wihA2[f] = pack2(wa, wa);
        wihB2[f] = pack2(wb, wb);
    }
    // biases seeded into the x-projection accumulators (both batch lanes)
    const float biasA = b_ih[rA] + b_hh[rA];
    const float biasB = b_ih[rB] + b_hh[rB];
    const ull biasA2 = pack2(biasA, biasA);
    const ull biasB2 = pack2(biasB, biasB);

    float c_reg = 0.0f;        // cell state of (batch bO, unit u)
    int p = 0;

    __syncthreads();           // only global sync: after init

    // ------- 16 AR iterations x 96 steps; the two halves never re-couple -------
    for (int k = 0; k < PRED; k++){
        for (int t = 0; t < SEQ; t++){
            // ---- x-projection first (bias included), packed over the batch pair ----
            ull xA = biasA2, xB = biasB2;
            {
                const float* xrow = &sh_xw[(k + t) * FEAT * BPB + 2 * bp];
                #pragma unroll
                for (int f = 0; f < FEAT; f++){
                    ull xx = *reinterpret_cast<const ull*>(xrow + f * BPB);
                    ffma2(xA, xx, wihA2[f]);
                    ffma2(xB, xx, wihB2[f]);
                }
            }
            float xa0, xa1, xb0, xb1;
            unpack2(xA, xa0, xa1);
            unpack2(xB, xb0, xb1);

            // ---- h-dot: accumulators seeded with (bias + x-proj) via MOV packs ----
            ull aA0 = pack2(xa0, 0.0f), aA1 = pack2(xa1, 0.0f);
            ull aB0 = pack2(xb0, 0.0f), aB1 = pack2(xb1, 0.0f);
            const ulonglong2* hE =
                reinterpret_cast<const ulonglong2*>(&h_sh[p][2*bp    ][0]);
            const ulonglong2* hO =
                reinterpret_cast<const ulonglong2*>(&h_sh[p][2*bp + 1][0]);
            #pragma unroll
            for (int c = 0; c < 16; c++){
                ulonglong2 u0 = hE[c];          // cols 4c..4c+3, batch even (broadcast)
                ulonglong2 u1 = hO[c];          // batch odd
                ffma2(aA0, u0.x, whhA[2*c]);
                ffma2(aB0, u0.x, whhB[2*c]);
                ffma2(aA0, u0.y, whhA[2*c+1]);
                ffma2(aB0, u0.y, whhB[2*c+1]);
                ffma2(aA1, u1.x, whhA[2*c]);
                ffma2(aB1, u1.x, whhB[2*c]);
                ffma2(aA1, u1.y, whhA[2*c+1]);
                ffma2(aB1, u1.y, whhB[2*c+1]);
            }
            float e, o;
            float vA0, vA1, vB0, vB1;
            unpack2(aA0, e, o); vA0 = e + o;   // rowA, batch even
            unpack2(aA1, e, o); vA1 = e + o;   // rowA, batch odd
            unpack2(aB0, e, o); vB0 = e + o;   // rowB, batch even
            unpack2(aB1, e, o); vB1 = e + o;   // rowB, batch odd

            // ---- pair exchange: 2 shfl.xor with lane^1 (gp partner) ----
            // gp0 owns batch even -> needs (g,o) even; sends (i,f) odd.
            // gp1 owns batch odd  -> needs (i,f) odd;  sends (g,o) even.
            float sA = gp ? vA0 : vA1;
            float sB = gp ? vB0 : vB1;
            float rAv = __shfl_xor_sync(0xffffffffu, sA, 1);
            float rBv = __shfl_xor_sync(0xffffffffu, sB, 1);
            float pi = gp ? rAv : vA0;
            float pf = gp ? rBv : vB0;
            float pg = gp ? vA1 : rAv;
            float po = gp ? vB1 : rBv;

            // ---- activations + cell update for (bO, u) ----
            float gi = sigmoid_fast(pi);
            float gf = sigmoid_fast(pf);
            float gg = tanhf_fast(pg);
            float go = sigmoid_fast(po);
            c_reg = fmaf(gf, c_reg, gi * gg);
            h_sh[p ^ 1][bO][u] = go * tanhf_fast(c_reg);

            asm volatile("bar.sync %0, 128;" :: "r"(barid) : "memory");
            p ^= 1;
        }

        // ---- per-half fc head: this half's 2 batches only ----
        if (tl < FEAT * 2){
            int bl = tl / FEAT;                // 0..1 within the half
            int o2 = tl - bl * FEAT;
            int b  = 2 * bp + bl;
            float acc = sh_fcb[o2];
            #pragma unroll
            for (int jj = 0; jj < HID; jj++)
                acc += h_sh[p][b][jj] * sh_fcW[o2 * HID + jj];
            out[(size_t)(b0 + b) * PRED * FEAT + k * FEAT + o2] = acc;
            sh_xw[((SEQ + k) * FEAT + o2) * BPB + b] = acc;
        }
        asm volatile("bar.sync %0, 128;" :: "r"(barid) : "memory");
    }
}

extern "C" void kernel_launch(void* const* d_in, const int* in_sizes, int n_in,
                              void* d_out, int out_size)
{
    const float* x    = (const float*)d_in[0];
    const float* W_ih = (const float*)d_in[1];
    const float* W_hh = (const float*)d_in[2];
    const float* b_ih = (const float*)d_in[3];
    const float* b_hh = (const float*)d_in[4];
    const float* fc_W = (const float*)d_in[5];
    const float* fc_b = (const float*)d_in[6];
    float* out = (float*)d_out;

    lstm_ar_kernel<<<NBLK, NTHR>>>(x, W_ih, W_hh, b_ih, b_hh, fc_W, fc_b, out);
}

// round 13
// speedup vs baseline: 1.4871x; 1.0171x over previous
#include <cuda_runtime.h>

#define SEQ   96
#define PRED  16
#define HID   64
#define FEAT  7
#define BPB   4               // batches per block
#define NBLK  128             // 512/4 — one block per SM, single wave
#define NTHR  256
#define WIN   (SEQ + PRED)

typedef unsigned long long ull;

static __device__ __forceinline__ ull pack2(float a, float b){
    ull r; asm("mov.b64 %0, {%1, %2};" : "=l"(r) : "f"(a), "f"(b)); return r;
}
static __device__ __forceinline__ void unpack2(ull v, float &a, float &b){
    asm("mov.b64 {%0, %1}, %2;" : "=f"(a), "=f"(b) : "l"(v));
}
// d = a*b + d, packed f32x2 (Blackwell FFMA2), exact fp32 per lane
static __device__ __forceinline__ void ffma2(ull &d, ull a, ull b){
    asm("fma.rn.f32x2 %0, %1, %2, %0;" : "+l"(d) : "l"(a), "l"(b));
}

static __device__ __forceinline__ float sigmoid_fast(float x){
    float e = __expf(-x);
    return __fdividef(1.0f, 1.0f + e);
}
static __device__ __forceinline__ float tanhf_fast(float x){
    float e = __expf(-2.0f * x);
    return __fdividef(2.0f, 1.0f + e) - 1.0f;
}

__global__ void __launch_bounds__(NTHR, 1)
lstm_ar_kernel(const float* __restrict__ x,
               const float* __restrict__ W_ih,
               const float* __restrict__ W_hh,
               const float* __restrict__ b_ih,
               const float* __restrict__ b_hh,
               const float* __restrict__ fc_W,
               const float* __restrict__ fc_b,
               float* __restrict__ out)
{
    // sliding input window: [t][feat][b], b in [0,4)  (per-batch columns)
    __shared__ float sh_xw[WIN * FEAT * BPB];
    // hidden state, double-buffered, batch-major: [buf][b][u]
    __shared__ float h_sh[2][BPB][HID];
    __shared__ float sh_fcW[FEAT * HID];
    __shared__ float sh_fcb[FEAT];

    const int tid = threadIdx.x;            // 0..255
    const int bp  = tid >> 7;               // batch pair (warp-aligned half)
    const int gp  = tid & 1;                // 0: rows i,f   1: rows g,o
    const int u   = (tid >> 1) & 63;        // hidden unit
    const int rA  = gp * 128 + u;           // i-row (gp0) / g-row (gp1)
    const int rB  = gp * 128 + 64 + u;      // f-row (gp0) / o-row (gp1)
    const int bO  = 2 * bp + gp;            // batch whose cell state this thread owns
    const int b0  = blockIdx.x * BPB;
    const int barid = 1 + bp;               // named barrier per independent half
    const int tl  = tid & 127;              // index within half

    // ---------------- one-time init ----------------
    for (int i = tid; i < SEQ * FEAT * BPB; i += NTHR){
        int b = i & 3;
        int q = i >> 2;
        int f = q % FEAT;
        int t = q / FEAT;
        sh_xw[(t * FEAT + f) * BPB + b] =
            x[(size_t)(b0 + b) * SEQ * FEAT + t * FEAT + f];
    }
    for (int i = tid; i < FEAT * HID; i += NTHR) sh_fcW[i] = fc_W[i];
    if (tid < FEAT) sh_fcb[tid] = fc_b[tid];
    {
        float* hz = &h_sh[0][0][0];
        for (int i = tid; i < 2 * BPB * HID; i += NTHR) hz[i] = 0.0f;
    }

    // W_hh rows rA, rB as natural column-pairs: 64 u64 = 128 regs
    ull whhA[HID / 2], whhB[HID / 2];
    {
        const ull* wa = reinterpret_cast<const ull*>(W_hh + (size_t)rA * HID);
        const ull* wb = reinterpret_cast<const ull*>(W_hh + (size_t)rB * HID);
        #pragma unroll
        for (int c = 0; c < HID / 2; c++){ whhA[c] = wa[c]; whhB[c] = wb[c]; }
    }
    // W_ih rows, splatted for batch-pair f32x2 x-projection
    ull wihA2[FEAT], wihB2[FEAT];
    #pragma unroll
    for (int f = 0; f < FEAT; f++){
        float wa = W_ih[rA * FEAT + f];
        float wb = W_ih[rB * FEAT + f];
        wihA2[f] = pack2(wa, wa);
        wihB2[f] = pack2(wb, wb);
    }
    // biases seeded into the x-projection accumulators (both batch lanes)
    const float biasA = b_ih[rA] + b_hh[rA];
    const float biasB = b_ih[rB] + b_hh[rB];
    const ull biasA2 = pack2(biasA, biasA);
    const ull biasB2 = pack2(biasB, biasB);

    float c_reg = 0.0f;        // cell state of (batch bO, unit u)
    int p = 0;

    __syncthreads();           // only global sync: after init

    // ------- 16 AR iterations x 96 steps; the two halves never re-couple -------
    for (int k = 0; k < PRED; k++){
        // prefetch x-projection for step t=0 (slot k; window stable within this k)
        ull xA = biasA2, xB = biasB2;
        {
            const float* xrow = &sh_xw[k * FEAT * BPB + 2 * bp];
            #pragma unroll
            for (int f = 0; f < FEAT; f++){
                ull xx = *reinterpret_cast<const ull*>(xrow + f * BPB);
                ffma2(xA, xx, wihA2[f]);
                ffma2(xB, xx, wihB2[f]);
            }
        }

        for (int t = 0; t < SEQ; t++){
            // ---- consume prefetched x-projection (bias already included) ----
            float xa0, xa1, xb0, xb1;
            unpack2(xA, xa0, xa1);
            unpack2(xB, xb0, xb1);

            // ---- h-dot: accumulators seeded with (bias + x-proj) via MOV packs ----
            ull aA0 = pack2(xa0, 0.0f), aA1 = pack2(xa1, 0.0f);
            ull aB0 = pack2(xb0, 0.0f), aB1 = pack2(xb1, 0.0f);
            const ulonglong2* hE =
                reinterpret_cast<const ulonglong2*>(&h_sh[p][2*bp    ][0]);
            const ulonglong2* hO =
                reinterpret_cast<const ulonglong2*>(&h_sh[p][2*bp + 1][0]);
            #pragma unroll
            for (int c = 0; c < 16; c++){
                ulonglong2 u0 = hE[c];          // cols 4c..4c+3, batch even (broadcast)
                ulonglong2 u1 = hO[c];          // batch odd
                ffma2(aA0, u0.x, whhA[2*c]);
                ffma2(aB0, u0.x, whhB[2*c]);
                ffma2(aA0, u0.y, whhA[2*c+1]);
                ffma2(aB0, u0.y, whhB[2*c+1]);
                ffma2(aA1, u1.x, whhA[2*c]);
                ffma2(aB1, u1.x, whhB[2*c]);
                ffma2(aA1, u1.y, whhA[2*c+1]);
                ffma2(aB1, u1.y, whhB[2*c+1]);
            }
            float e, o;
            float vA0, vA1, vB0, vB1;
            unpack2(aA0, e, o); vA0 = e + o;   // rowA, batch even
            unpack2(aA1, e, o); vA1 = e + o;   // rowA, batch odd
            unpack2(aB0, e, o); vB0 = e + o;   // rowB, batch even
            unpack2(aB1, e, o); vB1 = e + o;   // rowB, batch odd

            // ---- pair exchange: 2 shfl.xor with lane^1 (gp partner) ----
            // gp0 owns batch even -> needs (g,o) even; sends (i,f) odd.
            // gp1 owns batch odd  -> needs (i,f) odd;  sends (g,o) even.
            float sA = gp ? vA0 : vA1;
            float sB = gp ? vB0 : vB1;
            float rAv = __shfl_xor_sync(0xffffffffu, sA, 1);
            float rBv = __shfl_xor_sync(0xffffffffu, sB, 1);
            float pi = gp ? rAv : vA0;
            float pf = gp ? rBv : vB0;
            float pg = gp ? vA1 : rAv;
            float po = gp ? vB1 : rBv;

            // ---- activations + cell update for (bO, u) ----
            float gi = sigmoid_fast(pi);
            float gf = sigmoid_fast(pf);
            float gg = tanhf_fast(pg);
            float go = sigmoid_fast(po);
            c_reg = fmaf(gf, c_reg, gi * gg);
            h_sh[p ^ 1][bO][u] = go * tanhf_fast(c_reg);

            // ---- prefetch next step's x-projection INSIDE the barrier shadow ----
            // (window slots read here are stable for the whole k-iteration)
            if (t < SEQ - 1){
                xA = biasA2; xB = biasB2;
                const float* xrow = &sh_xw[(k + t + 1) * FEAT * BPB + 2 * bp];
                #pragma unroll
                for (int f = 0; f < FEAT; f++){
                    ull xx = *reinterpret_cast<const ull*>(xrow + f * BPB);
                    ffma2(xA, xx, wihA2[f]);
                    ffma2(xB, xx, wihB2[f]);
                }
            }

            asm volatile("bar.sync %0, 128;" :: "r"(barid) : "memory");
            p ^= 1;
        }

        // ---- per-half fc head: this half's 2 batches only ----
        if (tl < FEAT * 2){
            int bl = tl / FEAT;                // 0..1 within the half
            int o2 = tl - bl * FEAT;
            int b  = 2 * bp + bl;
            float acc = sh_fcb[o2];
            #pragma unroll
            for (int jj = 0; jj < HID; jj++)
                acc += h_sh[p][b][jj] * sh_fcW[o2 * HID + jj];
            out[(size_t)(b0 + b) * PRED * FEAT + k * FEAT + o2] = acc;
            sh_xw[((SEQ + k) * FEAT + o2) * BPB + b] = acc;
        }
        asm volatile("bar.sync %0, 128;" :: "r"(barid) : "memory");
    }
}

extern "C" void kernel_launch(void* const* d_in, const int* in_sizes, int n_in,
                              void* d_out, int out_size)
{
    const float* x    = (const float*)d_in[0];
    const float* W_ih = (const float*)d_in[1];
    const float* W_hh = (const float*)d_in[2];
    const float* b_ih = (const float*)d_in[3];
    const float* b_hh = (const float*)d_in[4];
    const float* fc_W = (const float*)d_in[5];
    const float* fc_b = (const float*)d_in[6];
    float* out = (float*)d_out;

    lstm_ar_kernel<<<NBLK, NTHR>>>(x, W_ih, W_hh, b_ih, b_hh, fc_W, fc_b, out);
}